// round 2
// baseline (speedup 1.0000x reference)
#include <cuda_runtime.h>

#define B_TOT  8192
#define NN     82
#define HH     10
#define NOUT   5
#define TSTEPS 3
#define GB     4            // batches per block
#define BD     352          // 11 warps; active threads = 82*4 = 328
#define NROW   12           // padded floats per (node, g) row -> 48B, 16B aligned

// shared-memory float offsets (all 16B-aligned)
#define SM_ADJ   0                           // 2*NN*NN interleaved (in,out) pairs
#define SM_NODES (2*NN*NN)                   // NN*GB*NROW
#define SM_W3W   (SM_NODES + NN*GB*NROW)     // 200
#define SM_W4W   (SM_W3W + 200)              // 200
#define SM_W5W   (SM_W4W + 200)              // 200
#define SM_WOUT  (SM_W5W + 200)              // 100 -> pad to 104 for alignment
#define SM_W3U   (SM_WOUT + 104)             // 120 (rows padded to 12)
#define SM_W5U   (SM_W3U + 120)              // 120
#define SM_BZ    (SM_W5U + 120)              // 16
#define SM_BR    (SM_BZ + 16)                // 16
#define SM_BH    (SM_BR + 16)                // 16
#define SM_BO    (SM_BH + 16)                // 16
#define SM_TOTAL (SM_BO + 16)

union F4U { float4 v; unsigned long long u[2]; float f[4]; };
union F2U { unsigned long long u; float2 f; };

__device__ __forceinline__ unsigned long long pack2(float a, float b) {
    unsigned long long r;
    asm("mov.b64 %0, {%1, %2};" : "=l"(r) : "f"(a), "f"(b));
    return r;
}
__device__ __forceinline__ void fma2(unsigned long long& acc,
                                     unsigned long long a, unsigned long long b) {
    asm("fma.rn.f32x2 %0, %1, %2, %0;" : "+l"(acc) : "l"(a), "l"(b));
}
__device__ __forceinline__ float hsum2(unsigned long long p) {
    F2U u; u.u = p; return u.f.x + u.f.y;
}

__device__ __forceinline__ float sigmoid_f(float v) {
    return __fdividef(1.0f, 1.0f + __expf(-v));
}
__device__ __forceinline__ float tanh_f(float v) {
    return __fdividef(2.0f, 1.0f + __expf(-2.0f * v)) - 1.0f;
}

// load 10 floats (16B-aligned base) as 5 f32x2 pairs: 2x LDS.128 + 1x LDS.64
__device__ __forceinline__ void load10(const float* p, unsigned long long* d) {
    F4U q0, q1; F2U q2;
    q0.v = *(const float4*)(p);
    q1.v = *(const float4*)(p + 4);
    q2.f = *(const float2*)(p + 8);
    d[0] = q0.u[0]; d[1] = q0.u[1]; d[2] = q1.u[0]; d[3] = q1.u[1]; d[4] = q2.u;
}

__global__ __launch_bounds__(BD, 2)
void ggnn_kernel(const float* __restrict__ x,
                 const float* __restrict__ in_adj,
                 const float* __restrict__ out_adj,
                 const float* __restrict__ w3w, const float* __restrict__ b3w,
                 const float* __restrict__ w3u, const float* __restrict__ b3u,
                 const float* __restrict__ w4w, const float* __restrict__ b4w,
                 const float* __restrict__ w5w, const float* __restrict__ b5w,
                 const float* __restrict__ w5u, const float* __restrict__ b5u,
                 const float* __restrict__ wout, const float* __restrict__ bout,
                 float* __restrict__ out0, float* __restrict__ outfn)
{
    extern __shared__ float sm[];
    const int tid = threadIdx.x;

    // ---- cooperative setup loads ----
    for (int idx = tid; idx < NN * NN; idx += BD) {
        sm[SM_ADJ + 2 * idx]     = in_adj[idx];
        sm[SM_ADJ + 2 * idx + 1] = out_adj[idx];
    }
    for (int idx = tid; idx < 200; idx += BD) {
        sm[SM_W3W + idx] = w3w[idx];
        sm[SM_W4W + idx] = w4w[idx];
        sm[SM_W5W + idx] = w5w[idx];
    }
    for (int idx = tid; idx < 100; idx += BD) {
        sm[SM_WOUT + idx] = wout[idx];
        int h = idx / 10, k = idx - 10 * h;
        sm[SM_W3U + h * 12 + k] = w3u[idx];
        sm[SM_W5U + h * 12 + k] = w5u[idx];
    }
    if (tid < HH) {
        sm[SM_BZ + tid] = b3w[tid] + b3u[tid];
        sm[SM_BR + tid] = b4w[tid] + b3u[tid];   // reference bug: r reuses b3u
        sm[SM_BH + tid] = b5w[tid] + b5u[tid];
    }
    if (tid < NOUT) sm[SM_BO + tid] = bout[tid];
    if (tid >= 100 && tid < 104) sm[SM_WOUT + tid] = 0.f;  // pad
    if (tid < 20) {   // zero padding lanes of u-rows so vector loads are safe
        sm[SM_W3U + (tid / 2) * 12 + 10 + (tid & 1)] = 0.f;
        sm[SM_W5U + (tid / 2) * 12 + 10 + (tid & 1)] = 0.f;
    }

    const int  i   = tid >> 2;       // node index
    const int  g   = tid & 3;        // batch-in-block
    const bool act = (tid < NN * GB);
    const int  b   = blockIdx.x * GB + g;

    float fn[HH];
    if (act) {
        const float* xr = x + ((size_t)b * NN + i) * HH;
        float* nr = sm + SM_NODES + (i * GB + g) * NROW;
        #pragma unroll
        for (int h = 0; h < HH; h++) { fn[h] = xr[h]; nr[h] = fn[h]; }
    }
    __syncthreads();

    for (int st = 0; st < TSTEPS; st++) {
        if (act) {
            // ---- aggregation: 10 packed accumulators, j unrolled by 2 ----
            unsigned long long avp[HH];   // [0..4]=a_in pairs, [5..9]=a_out pairs
            #pragma unroll
            for (int p = 0; p < HH; p++) avp[p] = 0ULL;

            const float* arow  = sm + SM_ADJ + i * (2 * NN);
            const float* nbase = sm + SM_NODES + g * NROW;
            #pragma unroll 2
            for (int j = 0; j < NN; j += 2) {
                F4U ab; ab.v = *(const float4*)(arow + 2 * j);   // in_j,out_j,in_j1,out_j1
                unsigned long long aa0 = pack2(ab.f[0], ab.f[0]);
                unsigned long long bb0 = pack2(ab.f[1], ab.f[1]);
                unsigned long long aa1 = pack2(ab.f[2], ab.f[2]);
                unsigned long long bb1 = pack2(ab.f[3], ab.f[3]);
                const float* x0 = nbase + j * (GB * NROW);
                const float* x1 = x0 + (GB * NROW);
                unsigned long long s0[5], s1[5];
                load10(x0, s0);
                load10(x1, s1);
                #pragma unroll
                for (int p = 0; p < 5; p++) {
                    fma2(avp[p],     aa0, s0[p]);
                    fma2(avp[5 + p], bb0, s0[p]);
                    fma2(avp[p],     aa1, s1[p]);
                    fma2(avp[5 + p], bb1, s1[p]);
                }
            }

            // fn as packed pairs
            unsigned long long fnp[5];
            #pragma unroll
            for (int p = 0; p < 5; p++) fnp[p] = pack2(fn[2 * p], fn[2 * p + 1]);

            // ---- gates z, r (packed dense) ----
            float zv[HH], rv[HH];
            #pragma unroll
            for (int h = 0; h < HH; h++) {
                unsigned long long u3r[5];
                load10(sm + SM_W3U + h * 12, u3r);
                unsigned long long uacc = 0ULL;
                #pragma unroll
                for (int p = 0; p < 5; p++) fma2(uacc, u3r[p], fnp[p]);
                float u3 = hsum2(uacc);

                unsigned long long zacc = 0ULL, racc = 0ULL;
                const float4* w3q = (const float4*)(sm + SM_W3W + h * 20);
                const float4* w4q = (const float4*)(sm + SM_W4W + h * 20);
                #pragma unroll
                for (int q = 0; q < 5; q++) {
                    F4U w3u_, w4u_;
                    w3u_.v = w3q[q];
                    w4u_.v = w4q[q];
                    fma2(zacc, w3u_.u[0], avp[2 * q]);
                    fma2(zacc, w3u_.u[1], avp[2 * q + 1]);
                    fma2(racc, w4u_.u[0], avp[2 * q]);
                    fma2(racc, w4u_.u[1], avp[2 * q + 1]);
                }
                zv[h] = sigmoid_f(sm[SM_BZ + h] + u3 + hsum2(zacc));
                rv[h] = sigmoid_f(sm[SM_BR + h] + u3 + hsum2(racc));  // ref bug: reuses u3
            }

            // rv * fn, packed
            unsigned long long rfp[5];
            #pragma unroll
            for (int p = 0; p < 5; p++)
                rfp[p] = pack2(rv[2 * p] * fn[2 * p], rv[2 * p + 1] * fn[2 * p + 1]);

            // ---- candidate h and state update ----
            #pragma unroll
            for (int h = 0; h < HH; h++) {
                unsigned long long hacc = 0ULL;
                const float4* w5q = (const float4*)(sm + SM_W5W + h * 20);
                #pragma unroll
                for (int q = 0; q < 5; q++) {
                    F4U w5u_;
                    w5u_.v = w5q[q];
                    fma2(hacc, w5u_.u[0], avp[2 * q]);
                    fma2(hacc, w5u_.u[1], avp[2 * q + 1]);
                }
                unsigned long long u5r[5];
                load10(sm + SM_W5U + h * 12, u5r);
                unsigned long long uacc = 0ULL;
                #pragma unroll
                for (int p = 0; p < 5; p++) fma2(uacc, u5r[p], rfp[p]);
                float hv = tanh_f(sm[SM_BH + h] + hsum2(hacc) + hsum2(uacc));
                fn[h] = fn[h] + zv[h] * (hv - fn[h]);   // (1-z)*fn + z*hv
            }
        }
        __syncthreads();   // all aggregation reads of s_nodes done
        if (act) {
            float* nr = sm + SM_NODES + (i * GB + g) * NROW;
            #pragma unroll
            for (int h = 0; h < HH; h++) nr[h] = fn[h];
        }
        __syncthreads();   // new states visible
    }

    // ---- output head: tanh(wout * [fn, x] + bout), plus fn itself ----
    if (act) {
        const float* xr = x + ((size_t)b * NN + i) * HH;
        unsigned long long fnp[5], xp[5];
        #pragma unroll
        for (int p = 0; p < 5; p++) {
            fnp[p] = pack2(fn[2 * p], fn[2 * p + 1]);
            xp[p]  = pack2(xr[2 * p], xr[2 * p + 1]);
        }

        const size_t row = (size_t)b * NN + i;
        float* op = out0 + row * NOUT;
        #pragma unroll
        for (int o = 0; o < NOUT; o++) {
            const float4* wq = (const float4*)(sm + SM_WOUT + o * 20);
            unsigned long long acc = 0ULL;
            #pragma unroll
            for (int q = 0; q < 5; q++) {
                F4U w_;
                w_.v = wq[q];
                unsigned long long opnd0 = (2 * q < 5)     ? fnp[2 * q]     : xp[2 * q - 5];
                unsigned long long opnd1 = (2 * q + 1 < 5) ? fnp[2 * q + 1] : xp[2 * q - 4];
                fma2(acc, w_.u[0], opnd0);
                fma2(acc, w_.u[1], opnd1);
            }
            op[o] = tanh_f(sm[SM_BO + o] + hsum2(acc));
        }
        float* fp = outfn + row * HH;
        #pragma unroll
        for (int h = 0; h < HH; h++) fp[h] = fn[h];
    }
}

extern "C" void kernel_launch(void* const* d_in, const int* in_sizes, int n_in,
                              void* d_out, int out_size)
{
    const float* x       = (const float*)d_in[0];
    const float* in_adj  = (const float*)d_in[1];
    const float* out_adj = (const float*)d_in[2];
    const float* w3w  = (const float*)d_in[3];
    const float* b3w  = (const float*)d_in[4];
    const float* w3u  = (const float*)d_in[5];
    const float* b3u  = (const float*)d_in[6];
    const float* w4w  = (const float*)d_in[7];
    const float* b4w  = (const float*)d_in[8];
    const float* w5w  = (const float*)d_in[9];
    const float* b5w  = (const float*)d_in[10];
    const float* w5u  = (const float*)d_in[11];
    const float* b5u  = (const float*)d_in[12];
    const float* wout = (const float*)d_in[13];
    const float* bout = (const float*)d_in[14];

    float* out0  = (float*)d_out;
    float* outfn = out0 + (size_t)B_TOT * NN * NOUT;

    const size_t smbytes = SM_TOTAL * sizeof(float);
    cudaFuncSetAttribute(ggnn_kernel,
                         cudaFuncAttributeMaxDynamicSharedMemorySize,
                         (int)smbytes);

    ggnn_kernel<<<B_TOT / GB, BD, smbytes>>>(
        x, in_adj, out_adj,
        w3w, b3w, w3u, b3u, w4w, b4w, w5w, b5w, w5u, b5u, wout, bout,
        out0, outfn);
}